// round 15
// baseline (speedup 1.0000x reference)
#include <cuda_runtime.h>
#include <cuda_fp16.h>
#include <math.h>

#define VOX   4096
#define TPTS  100
#define KNN   8

// pack: top 25 bits of order-flipped key | (127 - j).
// VALID ONLY because keys here are <= 0 (negdist/2): for sign-bit-set floats
// the order-preserving map ordf(u) == ~u. The lone near-zero (possibly +eps)
// self-key maps to the top of the order under ~u, which is where it belongs;
// only top-8 SET membership matters (we max over the 8).
__device__ __forceinline__ unsigned packkey(float key, int jcode) {
    return (~__float_as_uint(key) & 0xFFFFFF80u) | (unsigned)jcode;
}

__device__ __forceinline__ void cswap(unsigned& a, unsigned& b) {
    unsigned mx = a > b ? a : b;
    unsigned mn = a > b ? b : a;
    a = mx; b = mn;
}

// sort a bitonic 8-sequence into descending order (12 comparators)
__device__ __forceinline__ void bitonic8(unsigned v[KNN]) {
    cswap(v[0], v[4]); cswap(v[1], v[5]); cswap(v[2], v[6]); cswap(v[3], v[7]);
    cswap(v[0], v[2]); cswap(v[1], v[3]); cswap(v[4], v[6]); cswap(v[5], v[7]);
    cswap(v[0], v[1]); cswap(v[2], v[3]); cswap(v[4], v[5]); cswap(v[6], v[7]);
}

// merge sorted-desc w[8] into sorted-desc v[8], keeping top-8
__device__ __forceinline__ void merge8(unsigned v[KNN], const unsigned w[KNN]) {
#pragma unroll
    for (int i = 0; i < KNN; i++) {
        unsigned b = w[KNN - 1 - i];
        v[i] = v[i] > b ? v[i] : b;
    }
    bitonic8(v);
}

// single insert (short masked-fill loop only)
__device__ __forceinline__ void ins8p(unsigned v[KNN], unsigned d) {
#pragma unroll
    for (int s = 0; s < KNN; s++) {
        unsigned vs = v[s];
        v[s] = vs > d ? vs : d;
        d    = vs > d ? d : vs;
    }
}

__device__ __forceinline__ unsigned long long fma_f32x2(
    unsigned long long a, unsigned long long b, unsigned long long c) {
    unsigned long long d;
    asm("fma.rn.f32x2 %0, %1, %2, %3;" : "=l"(d) : "l"(a), "l"(b), "l"(c));
    return d;
}
__device__ __forceinline__ unsigned long long mul_f32x2(
    unsigned long long a, unsigned long long b) {
    unsigned long long d;
    asm("mul.rn.f32x2 %0, %1, %2;" : "=l"(d) : "l"(a), "l"(b));
    return d;
}
__device__ __forceinline__ unsigned long long pack2(float lo, float hi) {
    unsigned long long r;
    asm("mov.b64 %0, {%1, %2};" : "=l"(r) : "f"(lo), "f"(hi));
    return r;
}
__device__ __forceinline__ void unpack2(float& lo, float& hi, unsigned long long v) {
    asm("mov.b64 {%0, %1}, %2;" : "=f"(lo), "=f"(hi) : "l"(v));
}

// s_feat row (12 floats): [0..3]=(x,y,z,r)  [4..7]=(3x,3y,2z,r)
//                         [8]=-wxx/2 (-inf on masked/pad rows)  [9]=-xx9/2
__global__ __launch_bounds__(128, 10) void gcn_kernel(
    const float* __restrict__ features,   // [4096,100,4]
    const float* __restrict__ conv_w,     // [64,18]
    const float* __restrict__ bn_gamma,
    const float* __restrict__ bn_beta,
    const float* __restrict__ bn_mean,
    const float* __restrict__ bn_var,
    const int*   __restrict__ num_voxels, // [4096]
    const int*   __restrict__ coors,      // [4096,4]
    float*       __restrict__ out)        // [4096,64]
{
    __shared__ __align__(16) float s_feat[TPTS + 4][12];
    // 12.8 KB buffer: phase 3 = candidate lists (u32[4*TPTS][8]),
    //                 phase 2/4 = a' in fp16 (__half2[TPTS][32])
    __shared__ __align__(16) unsigned s_ab[TPTS * 32];
    __shared__ __align__(16) float s_wta[4 * 64];
    __shared__ __align__(16) float s_wtb[4 * 64];
    __shared__ __align__(16) float s_ca[64];
    __shared__ __align__(16) float s_cb[64];
    __shared__ __align__(8)  unsigned char s_idx[TPTS][KNN];
    __shared__ __align__(16) float s_scr[256];     // 4 warp-partials x 64 ch
    __shared__ float s_red[16];
    __shared__ float s_mean[3];

    const int tid  = threadIdx.x;
    const int warp = tid >> 5;
    const int lane = tid & 31;
    const int vox  = blockIdx.x;
    int nv = num_voxels[vox];
    if (nv < 1) nv = 1;
    if (nv > TPTS) nv = TPTS;

    const float cx = (float)coors[vox * 4 + 3] * 0.2f + 0.1f;
    const float cy = (float)coors[vox * 4 + 2] * 0.2f + (-39.9f);

    // ---- phase 1a: load + mean over first 3 channels ----
    float4 fv = make_float4(0.f, 0.f, 0.f, 0.f);
    if (tid < TPTS)
        fv = reinterpret_cast<const float4*>(features)[vox * TPTS + tid];
    float sx = (tid < TPTS) ? fv.x : 0.f;
    float sy = (tid < TPTS) ? fv.y : 0.f;
    float sz = (tid < TPTS) ? fv.z : 0.f;
#pragma unroll
    for (int o = 16; o > 0; o >>= 1) {
        sx += __shfl_down_sync(0xffffffffu, sx, o);
        sy += __shfl_down_sync(0xffffffffu, sy, o);
        sz += __shfl_down_sync(0xffffffffu, sz, o);
    }
    if (lane == 0) {
        s_red[warp] = sx; s_red[4 + warp] = sy; s_red[8 + warp] = sz;
    }
    __syncthreads();
    if (tid == 0) {
        float fnv = (float)nv;
        s_mean[0] = (s_red[0] + s_red[1] + s_red[2] + s_red[3]) / fnv;
        s_mean[1] = (s_red[4] + s_red[5] + s_red[6] + s_red[7]) / fnv;
        s_mean[2] = (s_red[8] + s_red[9] + s_red[10] + s_red[11]) / fnv;
    }
    __syncthreads();

    const float mx = s_mean[0], my = s_mean[1], mz = s_mean[2];

    // ---- phase 1b: build rows; masked (t>=nv) and pad rows get key -inf ----
    if (tid < TPTS + 4) {
        float* row = s_feat[tid];
        if (tid < nv) {
            float x = fv.x, y = fv.y, z = fv.z, r = fv.w;
            float f[9];
            f[0] = x;  f[1] = y;  f[2] = z;  f[3] = r;
            f[4] = x - mx;  f[5] = y - my;  f[6] = z - mz;
            f[7] = x - cx;  f[8] = y - cy;
            float xx9 = 0.f;
#pragma unroll
            for (int c = 0; c < 9; c++) xx9 = fmaf(f[c], f[c], xx9);
            float wxx = 3.f * x * x + 3.f * y * y + 2.f * z * z + r * r;
            row[0] = x;       row[1] = y;       row[2] = z;       row[3] = r;
            row[4] = 3.f * x; row[5] = 3.f * y; row[6] = 2.f * z; row[7] = r;
            row[8] = -0.5f * wxx;
            row[9] = -0.5f * xx9;
            row[10] = 0.f; row[11] = 0.f;
        } else {
#pragma unroll
            for (int c = 0; c < 12; c++) row[c] = 0.f;
            row[8] = -__int_as_float(0x7F800000);   // -inf key, never kept
        }
    }

    // ---- phase 1c: fold BN + m/c constants into 4-dim weights ----
    if (tid < 64) {
        const int o = tid;
        float scale = bn_gamma[o] * rsqrtf(bn_var[o] + 1e-3f);
        float w1[9], wd[9];
#pragma unroll
        for (int c = 0; c < 9; c++) {
            float a = conv_w[o * 18 + c] * scale;
            float b = conv_w[o * 18 + 9 + c] * scale;
            w1[c] = a;
            wd[c] = b - a;
        }
        s_wta[0 * 64 + o] = w1[0] + w1[4] + w1[7];
        s_wta[1 * 64 + o] = w1[1] + w1[5] + w1[8];
        s_wta[2 * 64 + o] = w1[2] + w1[6];
        s_wta[3 * 64 + o] = w1[3];
        s_ca[o] = -(mx * w1[4] + my * w1[5] + mz * w1[6] + cx * w1[7] + cy * w1[8]);
        s_wtb[0 * 64 + o] = wd[0] + wd[4] + wd[7];
        s_wtb[1 * 64 + o] = wd[1] + wd[5] + wd[8];
        s_wtb[2 * 64 + o] = wd[2] + wd[6];
        s_wtb[3 * 64 + o] = wd[3];
        s_cb[o] = -(mx * wd[4] + my * wd[5] + mz * wd[6] + cx * wd[7] + cy * wd[8])
                  + bn_beta[o] - bn_mean[o] * scale;
    }
    __syncthreads();

    // ---- phase 3: warp w owns 4-aligned j-range; lanes stride t (broadcast j) ----
    uint4* cand4 = reinterpret_cast<uint4*>(s_ab);  // [4*nv][2] uint4
    const int b0 = 4 * ((warp * nv) >> 4);
    const int b1 = (warp == 3) ? 4 * ((nv + 3) >> 2) : 4 * (((warp + 1) * nv) >> 4);

    for (int t = lane; t < nv; t += 32) {
        const float* trow = s_feat[t];
        const unsigned long long pa01 = pack2(trow[0], trow[1]);
        const unsigned long long pa23 = pack2(trow[2], trow[3]);
        const unsigned long long init = pack2(trow[8], 0.f);   // xt_h folded in

        unsigned v[KNN];
#pragma unroll
        for (int k = 0; k < KNN; k++) v[k] = 0u;

#pragma unroll 2
        for (int j = b0; j < b1; j += 4) {
            unsigned d[4];
            const int jj = 127 - j;
#pragma unroll
            for (int u = 0; u < 4; u++) {
                const float* row = s_feat[j + u];
                const ulonglong2 jv = *reinterpret_cast<const ulonglong2*>(row + 4);
                const float cj = row[8];
                unsigned long long acc = fma_f32x2(pa01, jv.x, init);
                acc = fma_f32x2(pa23, jv.y, acc);
                float lo, hi; unpack2(lo, hi, acc);
                float key = (lo + hi) + cj;
                d[u] = packkey(key, jj - u);
            }
            cswap(d[0], d[1]); cswap(d[2], d[3]);
            cswap(d[0], d[2]); cswap(d[1], d[3]); cswap(d[1], d[2]);
            v[4] = v[4] > d[3] ? v[4] : d[3];
            v[5] = v[5] > d[2] ? v[5] : d[2];
            v[6] = v[6] > d[1] ? v[6] : d[1];
            v[7] = v[7] > d[0] ? v[7] : d[0];
            bitonic8(v);
        }
        const int rowi = (warp * nv + t) * 2;
        cand4[rowi]     = make_uint4(v[0], v[1], v[2], v[3]);
        cand4[rowi + 1] = make_uint4(v[4], v[5], v[6], v[7]);
    }
    __syncthreads();

    // ---- merge 4 warp-lists (uint4 loads), fill masked analytically ----
    if (tid < nv) {
        const int t = tid;
        unsigned v[KNN], w[KNN];
        uint4 p0 = cand4[t * 2], p1 = cand4[t * 2 + 1];
        v[0] = p0.x; v[1] = p0.y; v[2] = p0.z; v[3] = p0.w;
        v[4] = p1.x; v[5] = p1.y; v[6] = p1.z; v[7] = p1.w;
#pragma unroll
        for (int q = 1; q < 4; q++) {
            uint4 q0 = cand4[(q * nv + t) * 2], q1 = cand4[(q * nv + t) * 2 + 1];
            w[0] = q0.x; w[1] = q0.y; w[2] = q0.z; w[3] = q0.w;
            w[4] = q1.x; w[5] = q1.y; w[6] = q1.z; w[7] = q1.w;
            merge8(v, w);
        }
        const float mkey = s_feat[t][9];                 // <= 0
        const unsigned mbase = ~__float_as_uint(mkey) & 0xFFFFFF80u;
        for (int jm = nv; jm < TPTS; jm++) {
            unsigned p = mbase | (unsigned)(127 - jm);
            if (!(p > v[KNN - 1])) break;
            ins8p(v, p);
        }
#pragma unroll
        for (int k = 0; k < KNN; k++)
            s_idx[t][k] = (unsigned char)(127u - (v[k] & 0x7Fu));
    }
    __syncthreads();

    // ---- phase 2: a'[t] = mask*(ca + p_t . wta) via f32x2 -> fp16x2 ----
    __half2* a16 = reinterpret_cast<__half2*>(s_ab);   // [TPTS][32] half2
    {
        const ulonglong2* wta2 = reinterpret_cast<const ulonglong2*>(s_wta);
        for (int p = tid; p < 50 * 16; p += 128) {
            int t  = p >> 4;
            int t2 = t + 50;
            int o4 = p & 15;
            float m1 = (t  < nv) ? 1.f : 0.f;
            float m2 = (t2 < nv) ? 1.f : 0.f;
            const float4 A1 = *reinterpret_cast<const float4*>(s_feat[t]);
            const float4 A2 = *reinterpret_cast<const float4*>(s_feat[t2]);
            float fs1[4] = {A1.x, A1.y, A1.z, A1.w};
            float fs2[4] = {A2.x, A2.y, A2.z, A2.w};
            const float4 c4 = *reinterpret_cast<const float4*>(&s_ca[o4 * 4]);
            unsigned long long acc1a = pack2(c4.x, c4.y), acc1b = pack2(c4.z, c4.w);
            unsigned long long acc2a = acc1a, acc2b = acc1b;
#pragma unroll
            for (int c = 0; c < 4; c++) {
                ulonglong2 wv = wta2[c * 16 + o4];
                unsigned long long f1 = pack2(fs1[c], fs1[c]);
                unsigned long long f2 = pack2(fs2[c], fs2[c]);
                acc1a = fma_f32x2(f1, wv.x, acc1a);
                acc1b = fma_f32x2(f1, wv.y, acc1b);
                acc2a = fma_f32x2(f2, wv.x, acc2a);
                acc2b = fma_f32x2(f2, wv.y, acc2b);
            }
            unsigned long long m1p = pack2(m1, m1), m2p = pack2(m2, m2);
            acc1a = mul_f32x2(acc1a, m1p);  acc1b = mul_f32x2(acc1b, m1p);
            acc2a = mul_f32x2(acc2a, m2p);  acc2b = mul_f32x2(acc2b, m2p);
            float e0, e1;
            unpack2(e0, e1, acc1a); a16[t  * 32 + o4 * 2]     = __floats2half2_rn(e0, e1);
            unpack2(e0, e1, acc1b); a16[t  * 32 + o4 * 2 + 1] = __floats2half2_rn(e0, e1);
            unpack2(e0, e1, acc2a); a16[t2 * 32 + o4 * 2]     = __floats2half2_rn(e0, e1);
            unpack2(e0, e1, acc2b); a16[t2 * 32 + o4 * 2 + 1] = __floats2half2_rn(e0, e1);
        }
    }
    __syncthreads();

    // ---- phase 4: fused LDS.64 gathers + PRMT idx; b' via f32x2; NO lrelu
    //      (monotone: max(0, max_t lrelu(h)) == max(0, max_t h)) ----
    {
        const int o4    = tid & 15;
        const int slice = tid >> 4;
        const uint2* a64 = reinterpret_cast<const uint2*>(s_ab);  // [TPTS][16] 8B
        const ulonglong2* wtb2 = reinterpret_cast<const ulonglong2*>(s_wtb);
        const __half2 hneg = __float2half2_rn(-60000.f);
        float4 rmax = make_float4(0.f, 0.f, 0.f, 0.f);
        for (int t = slice; t < nv; t += 16) {
            int t2 = t + 8;
            int t2c = (t2 < nv) ? t2 : t;
            const uint2 ia = *reinterpret_cast<const uint2*>(s_idx[t]);
            const uint2 ib = *reinterpret_cast<const uint2*>(s_idx[t2c]);
            __half2 ma0 = hneg, ma1 = hneg, mb0 = hneg, mb1 = hneg;
#pragma unroll
            for (int k = 0; k < KNN; k++) {
                unsigned wa = (k < 4) ? ia.x : ia.y;
                unsigned wb = (k < 4) ? ib.x : ib.y;
                int ja = (int)__byte_perm(wa, 0u, 0x4440u | (k & 3));
                int jb = (int)__byte_perm(wb, 0u, 0x4440u | (k & 3));
                uint2 pa = a64[ja * 16 + o4];
                uint2 pb = a64[jb * 16 + o4];
                ma0 = __hmax2(ma0, *reinterpret_cast<__half2*>(&pa.x));
                ma1 = __hmax2(ma1, *reinterpret_cast<__half2*>(&pa.y));
                mb0 = __hmax2(mb0, *reinterpret_cast<__half2*>(&pb.x));
                mb1 = __hmax2(mb1, *reinterpret_cast<__half2*>(&pb.y));
            }
            const float4 A1 = *reinterpret_cast<const float4*>(s_feat[t]);
            const float4 A2 = *reinterpret_cast<const float4*>(s_feat[t2c]);
            float fs1[4] = {A1.x, A1.y, A1.z, A1.w};
            float fs2[4] = {A2.x, A2.y, A2.z, A2.w};
            const float4 cb4 = *reinterpret_cast<const float4*>(&s_cb[o4 * 4]);
            unsigned long long b1a = pack2(cb4.x, cb4.y), b1b = pack2(cb4.z, cb4.w);
            unsigned long long b2a = b1a, b2b = b1b;
#pragma unroll
            for (int c = 0; c < 4; c++) {
                ulonglong2 wv = wtb2[c * 16 + o4];
                unsigned long long f1 = pack2(fs1[c], fs1[c]);
                unsigned long long f2 = pack2(fs2[c], fs2[c]);
                b1a = fma_f32x2(f1, wv.x, b1a);
                b1b = fma_f32x2(f1, wv.y, b1b);
                b2a = fma_f32x2(f2, wv.x, b2a);
                b2b = fma_f32x2(f2, wv.y, b2b);
            }
            float b1x, b1y, b1z, b1w, b2x, b2y, b2z, b2w;
            unpack2(b1x, b1y, b1a);  unpack2(b1z, b1w, b1b);
            unpack2(b2x, b2y, b2a);  unpack2(b2z, b2w, b2b);
            float2 fa0 = __half22float2(ma0), fa1 = __half22float2(ma1);
            float2 fb0 = __half22float2(mb0), fb1 = __half22float2(mb1);
            rmax.x = fmaxf(rmax.x, fmaxf(fa0.x + b1x, fb0.x + b2x));
            rmax.y = fmaxf(rmax.y, fmaxf(fa0.y + b1y, fb0.y + b2y));
            rmax.z = fmaxf(rmax.z, fmaxf(fa1.x + b1z, fb1.x + b2z));
            rmax.w = fmaxf(rmax.w, fmaxf(fa1.y + b1w, fb1.y + b2w));
        }
        // lanes xor-16 share o4 but hold the sibling slice: reduce in-warp
        rmax.x = fmaxf(rmax.x, __shfl_xor_sync(0xffffffffu, rmax.x, 16));
        rmax.y = fmaxf(rmax.y, __shfl_xor_sync(0xffffffffu, rmax.y, 16));
        rmax.z = fmaxf(rmax.z, __shfl_xor_sync(0xffffffffu, rmax.z, 16));
        rmax.w = fmaxf(rmax.w, __shfl_xor_sync(0xffffffffu, rmax.w, 16));
        if (lane < 16)
            reinterpret_cast<float4*>(s_scr)[warp * 16 + o4] = rmax;
    }
    __syncthreads();

    if (tid < 64) {
        float r = fmaxf(fmaxf(s_scr[tid], s_scr[64 + tid]),
                        fmaxf(s_scr[128 + tid], s_scr[192 + tid]));
        out[vox * 64 + tid] = r;
    }
}

extern "C" void kernel_launch(void* const* d_in, const int* in_sizes, int n_in,
                              void* d_out, int out_size) {
    const float* features   = (const float*)d_in[0];
    const float* conv_w     = (const float*)d_in[1];
    const float* bn_gamma   = (const float*)d_in[2];
    const float* bn_beta    = (const float*)d_in[3];
    const float* bn_mean    = (const float*)d_in[4];
    const float* bn_var     = (const float*)d_in[5];
    const int*   num_voxels = (const int*)d_in[6];
    const int*   coors      = (const int*)d_in[7];
    float*       out        = (float*)d_out;

    gcn_kernel<<<VOX, 128>>>(features, conv_w, bn_gamma, bn_beta, bn_mean, bn_var,
                             num_voxels, coors, out);
}